// round 17
// baseline (speedup 1.0000x reference)
#include <cuda_runtime.h>
#include <cuda_bf16.h>

// DynamicMaskHead fused kernel (R17):
//   New model: the kernel is FFMA-3reg pipe-throughput-bound (issue% is
//   invariant across 8/12/16 warps; counted FMA-pipe time ~= duration).
//   Fix: fma.rn.f32x2 (FFMA2) halves FMA-pipe issues. R14 proved FFMA2
//   correctness but P=4 packed blew the 255-reg ceiling; this is P=2 packed
//   (R13's proven skeleton): acc/a2/a3/f are 8 register-pairs each
//   (~110-140 natural regs), uncapped.
//
// Shapes (fixed): feats [2,8,100,152] f32, params [128,419] f32,
//                 out = 3 x [128,1,200,304] f32 concatenated (b,e,f).

#define Hh   100
#define Wd   152
#define HWd  15200
#define OH   200
#define OW   304
#define OT   24      // output rows per block tile (9 tiles)
#define LR   14      // max logits rows per tile (12 + 2 halo)
#define NPAR 419
#define NT   128     // threads per block

typedef unsigned long long u64t;
union F2 { u64t q; float2 f; };

#define FMA2(d, a, b, c) \
    asm("fma.rn.f32x2 %0, %1, %2, %3;" : "=l"(d) : "l"(a), "l"(b), "l"(c))
#define ADD2(d, a, b) \
    asm("add.rn.f32x2 %0, %1, %2;" : "=l"(d) : "l"(a), "l"(b))

// load 8 duplicated weight pairs (16 floats) from 16B-aligned smem: 4x LDS.128
__device__ __forceinline__ void ldp(const float* __restrict__ base, F2 w[8]) {
    const ulonglong2* p = reinterpret_cast<const ulonglong2*>(base);
    const ulonglong2 a = p[0], b = p[1], c = p[2], d = p[3];
    w[0].q = a.x; w[1].q = a.y; w[2].q = b.x; w[3].q = b.y;
    w[4].q = c.x; w[5].q = c.y; w[6].q = d.x; w[7].q = d.y;
}

__global__ void __launch_bounds__(NT)
dmh_kernel(const float* __restrict__ feats_b,
           const float* __restrict__ feats_e,
           const float* __restrict__ params,
           const float* __restrict__ locs,
           const float* __restrict__ soi_arr,
           const int*   __restrict__ im_inds,
           const int*   __restrict__ fpn,
           const int*   __restrict__ stride_ptr,
           float*       __restrict__ out,
           int n_inst)
{
    const int tid  = threadIdx.x;
    const int tile = blockIdx.x;
    const int inst = blockIdx.y;
    const int i0   = tile * OT;

    __shared__ __align__(16) float sp[NPAR];
    __shared__ __align__(16) float sl[3][LR][Wd];
    __shared__ u64t sxsq[8][NT];            // staged x2b: 8 ch x 1 pair
    // duplicated transposed weights [k][(c,c)] + duplicated bias/out vectors
    __shared__ __align__(16) float w1bD[160], w1eD[160];
    __shared__ __align__(16) float w2bD[128], w2eD[128], wf1D[128];
    __shared__ __align__(16) float b1bD[16], b1eD[16], b2bD[16], b2eD[16];
    __shared__ __align__(16) float w3bD[16], w3eD[16], wf2D[16], bf1D[16];

    const float* prow = params + inst * NPAR;
    for (int t = tid; t < NPAR; t += NT) sp[t] = prow[t];
    __syncthreads();

    // transpose weights to [k][c] with duplication (w,w) for f32x2 lanes
    if (tid < 80) {                               // w1 (10x8)
        const int k = tid >> 3, c = tid & 7;
        const float vb = sp[c * 10 + k];
        const float ve = sp[169 + c * 10 + k];
        w1bD[2 * tid] = vb; w1bD[2 * tid + 1] = vb;
        w1eD[2 * tid] = ve; w1eD[2 * tid + 1] = ve;
    }
    if (tid >= 64) {                              // w2/wf (8x8)
        const int t = tid - 64;
        const int k = t >> 3, c = t & 7;
        const float v2b = sp[80 + c * 8 + k];
        const float v2e = sp[249 + c * 8 + k];
        const float vf  = sp[338 + c * 8 + k];
        w2bD[2 * t] = v2b; w2bD[2 * t + 1] = v2b;
        w2eD[2 * t] = v2e; w2eD[2 * t + 1] = v2e;
        wf1D[2 * t] = vf;  wf1D[2 * t + 1] = vf;
    }
    if (tid < 8) {                                // duplicated bias/out vectors
        const float a = sp[144 + tid]; w3bD[2*tid] = a; w3bD[2*tid+1] = a;
        const float b = sp[313 + tid]; w3eD[2*tid] = b; w3eD[2*tid+1] = b;
        const float c = sp[152 + tid]; b1bD[2*tid] = c; b1bD[2*tid+1] = c;
        const float d = sp[321 + tid]; b1eD[2*tid] = d; b1eD[2*tid+1] = d;
        const float e = sp[160 + tid]; b2bD[2*tid] = e; b2bD[2*tid+1] = e;
        const float f = sp[329 + tid]; b2eD[2*tid] = f; b2eD[2*tid+1] = f;
        const float g = sp[402 + tid]; wf2D[2*tid] = g; wf2D[2*tid+1] = g;
        const float h = sp[410 + tid]; bf1D[2*tid] = h; bf1D[2*tid+1] = h;
    }

    const int   stride  = stride_ptr ? *stride_ptr : 8;
    const float fstride = (float)stride;
    const float halfs   = (float)(stride >> 1);

    const float ix  = locs[inst * 2 + 0];
    const float iy  = locs[inst * 2 + 1];
    const float inv = 1.0f / soi_arr[fpn[inst]];
    const int   im  = im_inds[inst];

    const int ybase = (i0 > 0) ? ((i0 - 1) >> 1) : 0;
    const int yend  = min(Hh - 1, ((i0 + OT - 2) >> 1) + 1);
    const int nrows = yend - ybase + 1;

    __syncthreads();

    const float b3b = sp[168], b3e = sp[337], bf2 = sp[418];

    const float* fbB = feats_b + (long long)im * 8 * HWd;
    const float* fbE = feats_e + (long long)im * 8 * HWd;

    // ---------------- Phase B: logits strip into smem ----------------
    const int ngroups = nrows * (Wd / 2);      // 76 column-pairs per row
#pragma unroll 1
    for (int g = tid; g < ngroups; g += NT) {
        const int srow = g / 76;
        const int c0   = (g - srow * 76) * 2;
        const int y    = ybase + srow;

        const float rely  = (iy - ((float)y * fstride + halfs)) * inv;
        const float relx0 = (ix - ((float)c0 * fstride + halfs)) * inv;
        F2 rxx, ryy;
        rxx.f = make_float2(relx0, relx0 - fstride * inv);
        ryy.f = make_float2(rely, rely);

        const int base = y * Wd + c0;
        F2 wq[8];

        // ================= PASS 1: body head =================
        {
            F2 f[8];
#pragma unroll
            for (int k = 0; k < 8; k++) {
                const float2 u = *(const float2*)(fbB + k * HWd + base);
                f[k].f = u;
            }

            F2 acc[8];
            ldp(b1bD, wq);
#pragma unroll
            for (int c = 0; c < 8; c++) acc[c] = wq[c];
            ldp(w1bD, wq);                         // k=0: relx
#pragma unroll
            for (int c = 0; c < 8; c++)
                FMA2(acc[c].q, wq[c].q, rxx.q, acc[c].q);
            ldp(w1bD + 16, wq);                    // k=1: rely
#pragma unroll
            for (int c = 0; c < 8; c++)
                FMA2(acc[c].q, wq[c].q, ryy.q, acc[c].q);
#pragma unroll
            for (int k = 0; k < 8; k++) {
                ldp(w1bD + 32 + k * 16, wq);
#pragma unroll
                for (int c = 0; c < 8; c++)
                    FMA2(acc[c].q, wq[c].q, f[k].q, acc[c].q);
            }
            // relu -> x1
#pragma unroll
            for (int c = 0; c < 8; c++) {
                acc[c].f.x = fmaxf(acc[c].f.x, 0.0f);
                acc[c].f.y = fmaxf(acc[c].f.y, 0.0f);
            }

            // layer2
            F2 a2[8];
            ldp(b2bD, wq);
#pragma unroll
            for (int c = 0; c < 8; c++) a2[c] = wq[c];
#pragma unroll
            for (int k = 0; k < 8; k++) {
                ldp(w2bD + k * 16, wq);
#pragma unroll
                for (int c = 0; c < 8; c++)
                    FMA2(a2[c].q, wq[c].q, acc[k].q, a2[c].q);
            }
            // layer3 + stage x2b
            ldp(w3bD, wq);
            F2 lb; lb.f = make_float2(b3b, b3b);
#pragma unroll
            for (int c = 0; c < 8; c++) {
                F2 r;
                r.f.x = fmaxf(a2[c].f.x, 0.0f);
                r.f.y = fmaxf(a2[c].f.y, 0.0f);
                sxsq[c][tid] = r.q;
                FMA2(lb.q, wq[c].q, r.q, lb.q);
            }
            *(float2*)&sl[0][srow][c0] = lb.f;
        }

        // ================= PASS 2: edge head + fused head =================
        {
            F2 f[8];
#pragma unroll
            for (int k = 0; k < 8; k++) {
                const float2 u = *(const float2*)(fbE + k * HWd + base);
                f[k].f = u;
            }

            F2 acc[8];
            ldp(b1eD, wq);
#pragma unroll
            for (int c = 0; c < 8; c++) acc[c] = wq[c];
            ldp(w1eD, wq);
#pragma unroll
            for (int c = 0; c < 8; c++)
                FMA2(acc[c].q, wq[c].q, rxx.q, acc[c].q);
            ldp(w1eD + 16, wq);
#pragma unroll
            for (int c = 0; c < 8; c++)
                FMA2(acc[c].q, wq[c].q, ryy.q, acc[c].q);
#pragma unroll
            for (int k = 0; k < 8; k++) {
                ldp(w1eD + 32 + k * 16, wq);
#pragma unroll
                for (int c = 0; c < 8; c++)
                    FMA2(acc[c].q, wq[c].q, f[k].q, acc[c].q);
            }
#pragma unroll
            for (int c = 0; c < 8; c++) {
                acc[c].f.x = fmaxf(acc[c].f.x, 0.0f);
                acc[c].f.y = fmaxf(acc[c].f.y, 0.0f);
            }

            F2 a2[8];
            ldp(b2eD, wq);
#pragma unroll
            for (int c = 0; c < 8; c++) a2[c] = wq[c];
#pragma unroll
            for (int k = 0; k < 8; k++) {
                ldp(w2eD + k * 16, wq);
#pragma unroll
                for (int c = 0; c < 8; c++)
                    FMA2(a2[c].q, wq[c].q, acc[k].q, a2[c].q);
            }
            // layer3-e + build fused input xf = relu(a2e) + x2b (into acc)
            ldp(w3eD, wq);
            F2 le; le.f = make_float2(b3e, b3e);
#pragma unroll
            for (int c = 0; c < 8; c++) {
                F2 r;
                r.f.x = fmaxf(a2[c].f.x, 0.0f);
                r.f.y = fmaxf(a2[c].f.y, 0.0f);
                FMA2(le.q, wq[c].q, r.q, le.q);
                ADD2(acc[c].q, r.q, sxsq[c][tid]);
            }
            *(float2*)&sl[1][srow][c0] = le.f;

            // fused head: 8 -> 8 (relu) -> 1
            F2 a3[8];
            ldp(bf1D, wq);
#pragma unroll
            for (int c = 0; c < 8; c++) a3[c] = wq[c];
#pragma unroll
            for (int k = 0; k < 8; k++) {
                ldp(wf1D + k * 16, wq);
#pragma unroll
                for (int c = 0; c < 8; c++)
                    FMA2(a3[c].q, wq[c].q, acc[k].q, a3[c].q);
            }
            ldp(wf2D, wq);
            F2 lf; lf.f = make_float2(bf2, bf2);
#pragma unroll
            for (int c = 0; c < 8; c++) {
                F2 r;
                r.f.x = fmaxf(a3[c].f.x, 0.0f);
                r.f.y = fmaxf(a3[c].f.y, 0.0f);
                FMA2(lf.q, wq[c].q, r.q, lf.q);
            }
            *(float2*)&sl[2][srow][c0] = lf.f;
        }
    }
    __syncthreads();

    // ---------------- Phase C: aligned_bilinear x2 + sigmoid ----------------
    const int rows_here = min(OT, OH - i0);
    const int npix      = rows_here * OW;
    const long long ostride = (long long)n_inst * OH * OW;
    float* ob = out + (long long)inst * (OH * OW);

#pragma unroll 1
    for (int idx = tid; idx < npix; idx += NT) {
        const int di = idx / OW;
        const int j  = idx - di * OW;
        const int i  = i0 + di;
        const int r  = (i > 0) ? i - 1 : 0;
        const int c  = (j > 0) ? j - 1 : 0;
        const int y0 = r >> 1;
        const int x0 = c >> 1;
        const float fy = (r & 1) ? 0.5f : 0.0f;
        const float fx = (c & 1) ? 0.5f : 0.0f;
        const int y1  = min(y0 + 1, Hh - 1);
        const int x1c = min(x0 + 1, Wd - 1);
        const int s0 = y0 - ybase;
        const int s1 = y1 - ybase;
        const int oidx = i * OW + j;

#pragma unroll
        for (int m = 0; m < 3; m++) {
            const float v00 = sl[m][s0][x0],  v01 = sl[m][s0][x1c];
            const float v10 = sl[m][s1][x0],  v11 = sl[m][s1][x1c];
            const float vt = v00 + fx * (v01 - v00);
            const float vb = v10 + fx * (v11 - v10);
            const float v  = vt + fy * (vb - vt);
            ob[m * ostride + oidx] = __fdividef(1.0f, 1.0f + __expf(-v));
        }
    }
}

extern "C" void kernel_launch(void* const* d_in, const int* in_sizes, int n_in,
                              void* d_out, int out_size)
{
    const float* feats_b = (const float*)d_in[0];
    const float* feats_e = (const float*)d_in[1];
    const float* params  = (const float*)d_in[2];
    const float* locs    = (const float*)d_in[3];
    const float* soi     = (const float*)d_in[4];
    const int*   im      = (const int*)d_in[5];
    const int*   fpn     = (const int*)d_in[6];
    const int*   stridep = (n_in > 7) ? (const int*)d_in[7] : nullptr;

    const int n_inst = in_sizes[5];                 // 128
    dim3 grid((OH + OT - 1) / OT, n_inst);          // 9 x 128
    dmh_kernel<<<grid, NT>>>(feats_b, feats_e, params, locs, soi,
                             im, fpn, stridep, (float*)d_out, n_inst);
}